// round 9
// baseline (speedup 1.0000x reference)
#include <cuda_runtime.h>
#include <math.h>
#include <stdint.h>

// Problem constants
#define B_   2
#define T_   2048
#define D_   768
#define H_   12
#define DK_  64
#define MTOK (B_*T_)          // 4096
#define ROWS_ (B_*H_*T_)      // 49152
#define NTILES 16             // T_/128 score col-tiles per row
#define KPAD 20               // 16 k-words + 4 pad (conflict-free ldmatrix)
#define CN   32               // av_recompute column chunk
#define QPITCH 68             // 64 k-words + 4
#define WPITCH 36             // 32 k-words + 4

// Scratch (allocation-free: __device__ globals)
__device__ float g_Q[MTOK*D_];
__device__ float g_K[MTOK*D_];
__device__ float g_V[MTOK*D_];
__device__ float g_attn[MTOK*D_];
__device__ float g_wts_fallback[(size_t)B_*H_*T_*T_];
__device__ float2 g_stats[(size_t)ROWS_*NTILES];

struct Batch3 { const float* A[3]; const float* Bm[3]; float* C[3]; };

// ---------------------------------------------------------------------------
__device__ __forceinline__ uint32_t f2tf32(float x) {
    uint32_t u;
    asm("cvt.rna.tf32.f32 %0, %1;" : "=r"(u) : "f"(x));
    return u;
}

__device__ __forceinline__ void mma16n8k8(float* c, const uint32_t* a, const uint32_t* b) {
    asm volatile(
        "mma.sync.aligned.m16n8k8.row.col.f32.tf32.tf32.f32 "
        "{%0,%1,%2,%3}, {%4,%5,%6,%7}, {%8,%9}, {%0,%1,%2,%3};\n"
        : "+f"(c[0]), "+f"(c[1]), "+f"(c[2]), "+f"(c[3])
        : "r"(a[0]), "r"(a[1]), "r"(a[2]), "r"(a[3]), "r"(b[0]), "r"(b[1]));
}

__device__ __forceinline__ void ldsm4(uint32_t& r0, uint32_t& r1, uint32_t& r2, uint32_t& r3,
                                      uint32_t addr) {
    asm volatile("ldmatrix.sync.aligned.m8n8.x4.shared.b16 {%0,%1,%2,%3}, [%4];"
                 : "=r"(r0), "=r"(r1), "=r"(r2), "=r"(r3) : "r"(addr));
}

__device__ __forceinline__ uint32_t cvta_smem(const void* p) {
    return (uint32_t)__cvta_generic_to_shared(p);
}

// ---------------------------------------------------------------------------
// tf32 NT GEMM, k-major smem + ldmatrix + register double buffering.
//   C[m,n] = alpha * sum_k A[m,k]*B[n,k]
// STATS: emit per-(row, 128-col-tile) (max, sum_exp). WRITEC: store C.
// ---------------------------------------------------------------------------
template<int BM, int BN, int WM, int WN, bool STATS, bool WRITEC>
__global__ __launch_bounds__((BM/WM)*(BN/WN)*32) void gemm_tf32(
    Batch3 bat, int K, int lda, int ldb, int ldc, float alpha, int innerCount,
    long aSI, long bSI, long cSI, float2* __restrict__ stats)
{
    constexpr int BK      = 16;
    constexpr int WARPS_M = BM / WM;
    constexpr int WARPS_N = BN / WN;
    constexpr int NT      = WARPS_M * WARPS_N * 32;
    constexpr int MT      = WM / 16;
    constexpr int NTL     = WN / 8;
    constexpr int AIT     = (BM * 4) / NT;
    constexpr int BIT     = (BN * 4) / NT;

    const int bz = blockIdx.z;
    const int bo = bz / innerCount, bi = bz % innerCount;
    const float* A  = bat.A[bo]  + (long)bi * aSI;
    const float* Bm = bat.Bm[bo] + (long)bi * bSI;
    float*       C  = bat.C[bo]  + (long)bi * cSI;

    __shared__ uint32_t As[2][BM][KPAD];
    __shared__ uint32_t Bs[2][BN][KPAD];
    __shared__ float    sred[WARPS_N][BM];

    const int tid  = threadIdx.x;
    const int lane = tid & 31;
    const int w    = tid >> 5;
    const int wm   = w % WARPS_M;
    const int wn   = w / WARPS_M;
    const int grp  = lane >> 2;
    const int tig  = lane & 3;

    const int row0 = blockIdx.y * BM;
    const int col0 = blockIdx.x * BN;

    uint32_t aAddr[MT], bAddr[NTL / 2];
    {
        const int rsel  = lane & 15;
        const int csel  = (lane & 16) >> 2;
        const int nsel  = (lane & 7) + ((lane & 16) ? 8 : 0);
        const int cselB = (lane & 8) ? 4 : 0;
#pragma unroll
        for (int im = 0; im < MT; im++)
            aAddr[im] = cvta_smem(&As[0][wm * WM + im * 16 + rsel][csel]);
#pragma unroll
        for (int ip = 0; ip < NTL / 2; ip++)
            bAddr[ip] = cvta_smem(&Bs[0][wn * WN + ip * 16 + nsel][cselB]);
    }
    constexpr uint32_t ABYTES = BM * KPAD * 4;
    constexpr uint32_t BBYTES = BN * KPAD * 4;

    float acc[MT][NTL][4];
#pragma unroll
    for (int i = 0; i < MT; i++)
#pragma unroll
        for (int j = 0; j < NTL; j++)
#pragma unroll
            for (int e = 0; e < 4; e++) acc[i][j][e] = 0.0f;

    float4 ra[AIT], rb[BIT];

    auto LDG = [&](int k0) {
#pragma unroll
        for (int it = 0; it < AIT; it++) {
            int j = tid + it * NT;
            int m = j >> 2, kq = (j & 3) << 2;
            ra[it] = *reinterpret_cast<const float4*>(&A[(long)(row0 + m) * lda + k0 + kq]);
        }
#pragma unroll
        for (int it = 0; it < BIT; it++) {
            int j = tid + it * NT;
            int n = j >> 2, kq = (j & 3) << 2;
            rb[it] = *reinterpret_cast<const float4*>(&Bm[(long)(col0 + n) * ldb + k0 + kq]);
        }
    };

    auto STS = [&](int buf) {
#pragma unroll
        for (int it = 0; it < AIT; it++) {
            int j = tid + it * NT;
            int m = j >> 2, kq = (j & 3) << 2;
            uint4 s;
            s.x = f2tf32(ra[it].x); s.y = f2tf32(ra[it].y);
            s.z = f2tf32(ra[it].z); s.w = f2tf32(ra[it].w);
            *reinterpret_cast<uint4*>(&As[buf][m][kq]) = s;
        }
#pragma unroll
        for (int it = 0; it < BIT; it++) {
            int j = tid + it * NT;
            int n = j >> 2, kq = (j & 3) << 2;
            uint4 s;
            s.x = f2tf32(rb[it].x); s.y = f2tf32(rb[it].y);
            s.z = f2tf32(rb[it].z); s.w = f2tf32(rb[it].w);
            *reinterpret_cast<uint4*>(&Bs[buf][n][kq]) = s;
        }
    };

    const int nIter = K >> 4;
    LDG(0);
    STS(0);
    __syncthreads();

    for (int t = 0; t < nIter; t++) {
        const int buf = t & 1;
        if (t + 1 < nIter) LDG((t + 1) << 4);
        const uint32_t aoff = buf ? ABYTES : 0u;
        const uint32_t boff = buf ? BBYTES : 0u;
#pragma unroll
        for (int ks = 0; ks < 2; ks++) {
            uint32_t af[MT][4];
            uint32_t bf[NTL][2];
#pragma unroll
            for (int im = 0; im < MT; im++)
                ldsm4(af[im][0], af[im][1], af[im][2], af[im][3],
                      aAddr[im] + aoff + ks * 32);
#pragma unroll
            for (int ip = 0; ip < NTL / 2; ip++) {
                uint32_t r0, r1, r2, r3;
                ldsm4(r0, r1, r2, r3, bAddr[ip] + boff + ks * 32);
                bf[2 * ip][0]     = r0; bf[2 * ip][1]     = r1;
                bf[2 * ip + 1][0] = r2; bf[2 * ip + 1][1] = r3;
            }
#pragma unroll
            for (int im = 0; im < MT; im++)
#pragma unroll
                for (int in = 0; in < NTL; in++)
                    mma16n8k8(acc[im][in], af[im], bf[in]);
        }
        if (t + 1 < nIter) STS(buf ^ 1);
        __syncthreads();
    }

#pragma unroll
    for (int im = 0; im < MT; im++)
#pragma unroll
        for (int in = 0; in < NTL; in++)
#pragma unroll
            for (int e = 0; e < 4; e++) acc[im][in][e] *= alpha;

    if (STATS) {
        float mx[MT][2];
#pragma unroll
        for (int im = 0; im < MT; im++) {
            float m0 = -INFINITY, m1 = -INFINITY;
#pragma unroll
            for (int in = 0; in < NTL; in++) {
                m0 = fmaxf(m0, fmaxf(acc[im][in][0], acc[im][in][1]));
                m1 = fmaxf(m1, fmaxf(acc[im][in][2], acc[im][in][3]));
            }
#pragma unroll
            for (int o = 1; o <= 2; o <<= 1) {
                m0 = fmaxf(m0, __shfl_xor_sync(0xffffffffu, m0, o));
                m1 = fmaxf(m1, __shfl_xor_sync(0xffffffffu, m1, o));
            }
            mx[im][0] = m0; mx[im][1] = m1;
        }
        if (tig == 0) {
#pragma unroll
            for (int im = 0; im < MT; im++) {
                sred[wn][wm * WM + im * 16 + grp]     = mx[im][0];
                sred[wn][wm * WM + im * 16 + grp + 8] = mx[im][1];
            }
        }
        __syncthreads();
        float rmax[MT][2];
#pragma unroll
        for (int im = 0; im < MT; im++)
#pragma unroll
            for (int h = 0; h < 2; h++) {
                int r = wm * WM + im * 16 + grp + h * 8;
                float m = sred[0][r];
#pragma unroll
                for (int ww = 1; ww < WARPS_N; ww++) m = fmaxf(m, sred[ww][r]);
                rmax[im][h] = m;
            }
        __syncthreads();
        float sm[MT][2];
#pragma unroll
        for (int im = 0; im < MT; im++) {
            float s0 = 0.f, s1 = 0.f;
#pragma unroll
            for (int in = 0; in < NTL; in++) {
                s0 += __expf(acc[im][in][0] - rmax[im][0]) + __expf(acc[im][in][1] - rmax[im][0]);
                s1 += __expf(acc[im][in][2] - rmax[im][1]) + __expf(acc[im][in][3] - rmax[im][1]);
            }
#pragma unroll
            for (int o = 1; o <= 2; o <<= 1) {
                s0 += __shfl_xor_sync(0xffffffffu, s0, o);
                s1 += __shfl_xor_sync(0xffffffffu, s1, o);
            }
            sm[im][0] = s0; sm[im][1] = s1;
        }
        if (tig == 0) {
#pragma unroll
            for (int im = 0; im < MT; im++) {
                sred[wn][wm * WM + im * 16 + grp]     = sm[im][0];
                sred[wn][wm * WM + im * 16 + grp + 8] = sm[im][1];
            }
        }
        __syncthreads();
        if (wn == 0 && tig == 0) {
#pragma unroll
            for (int im = 0; im < MT; im++)
#pragma unroll
                for (int h = 0; h < 2; h++) {
                    int r = wm * WM + im * 16 + grp + h * 8;
                    float s = sred[0][r];
#pragma unroll
                    for (int ww = 1; ww < WARPS_N; ww++) s += sred[ww][r];
                    stats[((long)bz * T_ + row0 + r) * NTILES + blockIdx.x] =
                        make_float2(rmax[im][h], s);
                }
        }
    }

    if (WRITEC) {
#pragma unroll
        for (int im = 0; im < MT; im++) {
            int r = row0 + wm * WM + im * 16 + grp;
#pragma unroll
            for (int in = 0; in < NTL; in++) {
                int cc = col0 + wn * WN + in * 8 + 2 * tig;
                *reinterpret_cast<float2*>(&C[(long)r       * ldc + cc]) =
                    make_float2(acc[im][in][0], acc[im][in][1]);
                *reinterpret_cast<float2*>(&C[(long)(r + 8) * ldc + cc]) =
                    make_float2(acc[im][in][2], acc[im][in][3]);
            }
        }
    }
}

// ===========================================================================
// av_recompute: per (b,h, 128-row block):
//   merge stats -> (M, 1/S); Q tile persistent in smem;
//   for each 32-col chunk: S = Q*K^T (tensor), w = exp(S/8 - M)/S_row,
//   write w (final weights), smem-bounce w, O += w * V (tensor).
// Warps: 4 x 2.  S warp tile 32x16; O warp tile 32x32.
// ===========================================================================
#define AV2_SMEM (128*QPITCH*4 + CN*QPITCH*4 + 64*WPITCH*4 + 128*WPITCH*4 + 2*128*4)

__global__ __launch_bounds__(256) void av_recompute(
    const float* __restrict__ Q, const float* __restrict__ Kg,
    const float* __restrict__ V, float* __restrict__ wts,
    const float2* __restrict__ stats, float* __restrict__ O)
{
    extern __shared__ char sm_[];
    uint32_t* Qs = reinterpret_cast<uint32_t*>(sm_);       // [128][QPITCH]
    uint32_t* Ks = Qs + 128 * QPITCH;                      // [CN][QPITCH]
    uint32_t* Vs = Ks + CN * QPITCH;                       // [64][WPITCH]
    uint32_t* Ws = Vs + 64 * WPITCH;                       // [128][WPITCH]
    float* sM = reinterpret_cast<float*>(Ws + 128 * WPITCH);
    float* sI = sM + 128;

    const int z = blockIdx.z;
    const int b = z / H_, h = z % H_;
    const int row0 = blockIdx.y * 128;
    const long gr = (long)z * T_ + row0;

    float* wout = wts + (long)z * T_ * T_ + (long)row0 * T_;
    const float* Qb = Q  + ((long)b * T_ + row0) * D_ + h * DK_;
    const float* Kb = Kg + (long)b * T_ * D_ + h * DK_;
    const float* Vb = V  + (long)b * T_ * D_ + h * DK_;

    const int tid  = threadIdx.x;
    const int lane = tid & 31;
    const int w    = tid >> 5;
    const int wm   = w & 3;       // 4 warps along M
    const int wn   = w >> 2;      // 2 warps along N
    const int grp  = lane >> 2;
    const int tig  = lane & 3;

    // --- stats merge for this block's 128 rows ---
    if (tid < 128) {
        const float4* sp = reinterpret_cast<const float4*>(stats + (gr + tid) * NTILES);
        float2 vv[NTILES];
#pragma unroll
        for (int i = 0; i < NTILES / 2; i++) {
            float4 t = sp[i];
            vv[2 * i]     = make_float2(t.x, t.y);
            vv[2 * i + 1] = make_float2(t.z, t.w);
        }
        float M = vv[0].x;
#pragma unroll
        for (int i = 1; i < NTILES; i++) M = fmaxf(M, vv[i].x);
        float S = 0.f;
#pragma unroll
        for (int i = 0; i < NTILES; i++) S += __expf(vv[i].x - M) * vv[i].y;
        sM[tid] = M;
        sI[tid] = 1.0f / S;
    }

    // --- Q tile load: [128][64] k-major ---
#pragma unroll
    for (int it = 0; it < 8; it++) {
        int j = tid + it * 256;
        int m = j >> 4, kq = (j & 15) << 2;
        float4 t = *reinterpret_cast<const float4*>(&Qb[(long)m * D_ + kq]);
        uint4 s;
        s.x = f2tf32(t.x); s.y = f2tf32(t.y); s.z = f2tf32(t.z); s.w = f2tf32(t.w);
        *reinterpret_cast<uint4*>(&Qs[m * QPITCH + kq]) = s;
    }

    // ldmatrix addresses
    const int rsel  = lane & 15;
    const int csel  = (lane & 16) >> 2;
    const int nsel  = (lane & 7) + ((lane & 16) ? 8 : 0);
    const int cselB = (lane & 8) ? 4 : 0;
    uint32_t aQ[2], aW[2], bK, bV[2];
#pragma unroll
    for (int im = 0; im < 2; im++) {
        aQ[im] = cvta_smem(&Qs[(wm * 32 + im * 16 + rsel) * QPITCH + csel]);
        aW[im] = cvta_smem(&Ws[(wm * 32 + im * 16 + rsel) * WPITCH + csel]);
    }
    bK = cvta_smem(&Ks[(wn * 16 + nsel) * QPITCH + cselB]);
#pragma unroll
    for (int ip = 0; ip < 2; ip++)
        bV[ip] = cvta_smem(&Vs[(wn * 32 + ip * 16 + nsel) * WPITCH + cselB]);

    float oacc[2][4][4];
#pragma unroll
    for (int i = 0; i < 2; i++)
#pragma unroll
        for (int j = 0; j < 4; j++)
#pragma unroll
            for (int e = 0; e < 4; e++) oacc[i][j][e] = 0.0f;

    float4 rk[2], rv[2];
    auto LDKV = [&](int c0) {
#pragma unroll
        for (int it = 0; it < 2; it++) {
            int j = tid + it * 256;
            int r = j >> 4, kq = (j & 15) << 2;
            rk[it] = *reinterpret_cast<const float4*>(&Kb[(long)(c0 + r) * D_ + kq]);
            rv[it] = *reinterpret_cast<const float4*>(&Vb[(long)(c0 + r) * D_ + kq]);
        }
    };
    auto STK = [&]() {
#pragma unroll
        for (int it = 0; it < 2; it++) {
            int j = tid + it * 256;
            int r = j >> 4, kq = (j & 15) << 2;
            uint4 s;
            s.x = f2tf32(rk[it].x); s.y = f2tf32(rk[it].y);
            s.z = f2tf32(rk[it].z); s.w = f2tf32(rk[it].w);
            *reinterpret_cast<uint4*>(&Ks[r * QPITCH + kq]) = s;
        }
    };
    auto STV = [&]() {
#pragma unroll
        for (int it = 0; it < 2; it++) {
            int j = tid + it * 256;
            int sc = j >> 4, nq = (j & 15) << 2;
            const float* pv = &rv[it].x;
#pragma unroll
            for (int e = 0; e < 4; e++)
                Vs[(nq + e) * WPITCH + sc] = f2tf32(pv[e]);
        }
    };

    LDKV(0);
    STK();
    STV();
    __syncthreads();    // Qs, Ks, Vs, sM/sI ready

    // loop-invariant per-thread row stats
    float Mv[2][2], Iv[2][2];
#pragma unroll
    for (int im = 0; im < 2; im++)
#pragma unroll
        for (int hh = 0; hh < 2; hh++) {
            int r = wm * 32 + im * 16 + grp + hh * 8;
            Mv[im][hh] = sM[r];
            Iv[im][hh] = sI[r];
        }

    const int nIter = T_ / CN;   // 64
    for (int t = 0; t < nIter; t++) {
        const int c0 = t * CN;
        if (t + 1 < nIter) LDKV(c0 + CN);

        // --- S-GEMM: S[128x32] = Q * K_chunk^T  (K depth 64 = 8 k8 steps) ---
        float sacc[2][2][4];
#pragma unroll
        for (int i = 0; i < 2; i++)
#pragma unroll
            for (int j = 0; j < 2; j++)
#pragma unroll
                for (int e = 0; e < 4; e++) sacc[i][j][e] = 0.0f;
#pragma unroll
        for (int ks = 0; ks < 8; ks++) {
            uint32_t af[2][4], bf[2][2];
#pragma unroll
            for (int im = 0; im < 2; im++)
                ldsm4(af[im][0], af[im][1], af[im][2], af[im][3], aQ[im] + ks * 32);
            {
                uint32_t r0, r1, r2, r3;
                ldsm4(r0, r1, r2, r3, bK + ks * 32);
                bf[0][0] = r0; bf[0][1] = r1; bf[1][0] = r2; bf[1][1] = r3;
            }
#pragma unroll
            for (int im = 0; im < 2; im++)
#pragma unroll
                for (int in = 0; in < 2; in++)
                    mma16n8k8(sacc[im][in], af[im], bf[in]);
        }

        // --- normalize, write final weights, stage into Ws ---
#pragma unroll
        for (int im = 0; im < 2; im++) {
            int rl = wm * 32 + im * 16 + grp;
#pragma unroll
            for (int in = 0; in < 2; in++) {
                int ccl = wn * 16 + in * 8 + 2 * tig;
                float w0 = __expf(sacc[im][in][0] * 0.125f - Mv[im][0]) * Iv[im][0];
                float w1 = __expf(sacc[im][in][1] * 0.125f - Mv[im][0]) * Iv[im][0];
                float w2 = __expf(sacc[im][in][2] * 0.125f - Mv[im][1]) * Iv[im][1];
                float w3 = __expf(sacc[im][in][3] * 0.125f - Mv[im][1]) * Iv[im][1];
                __stcs(reinterpret_cast<float2*>(&wout[(long)rl * T_ + c0 + ccl]),
                       make_float2(w0, w1));
                __stcs(reinterpret_cast<float2*>(&wout[(long)(rl + 8) * T_ + c0 + ccl]),
                       make_float2(w2, w3));
                uint2 p0; p0.x = f2tf32(w0); p0.y = f2tf32(w1);
                uint2 p1; p1.x = f2tf32(w2); p1.y = f2tf32(w3);
                *reinterpret_cast<uint2*>(&Ws[rl * WPITCH + ccl])       = p0;
                *reinterpret_cast<uint2*>(&Ws[(rl + 8) * WPITCH + ccl]) = p1;
            }
        }
        __syncthreads();   // Ws ready; all S-GEMM reads of Ks done

        if (t + 1 < nIter) STK();   // Ks not read by AV-GEMM

        // --- AV-GEMM: O[128x64] += Ws[128x32] * Vs  (4 k8 steps) ---
#pragma unroll
        for (int ks = 0; ks < 4; ks++) {
            uint32_t af[2][4], bf[4][2];
#pragma unroll
            for (int im = 0; im < 2; im++)
                ldsm4(af[im][0], af[im][1], af[im][2], af[im][3], aW[im] + ks * 32);
#pragma unroll
            for (int ip = 0; ip < 2; ip++) {
                uint32_t r0, r1, r2, r3;
                ldsm4(r0, r1, r2, r3, bV[ip] + ks * 32);
                bf[2 * ip][0]     = r0; bf[2 * ip][1]     = r1;
                bf[2 * ip + 1][0] = r2; bf[2 * ip + 1][1] = r3;
            }
#pragma unroll
            for (int im = 0; im < 2; im++)
#pragma unroll
                for (int in = 0; in < 4; in++)
                    mma16n8k8(oacc[im][in], af[im], bf[in]);
        }
        __syncthreads();   // Vs/Ws reads done

        if (t + 1 < nIter) STV();
    }

    // --- write O block [128 x 64] into attn layout [B*T, D] ---
#pragma unroll
    for (int im = 0; im < 2; im++) {
        int r = row0 + wm * 32 + im * 16 + grp;
#pragma unroll
        for (int in = 0; in < 4; in++) {
            int cc = wn * 32 + in * 8 + 2 * tig;
            float* op = &O[((long)b * T_ + r) * D_ + h * DK_ + cc];
            *reinterpret_cast<float2*>(op)            = make_float2(oacc[im][in][0], oacc[im][in][1]);
            *reinterpret_cast<float2*>(op + 8LL * D_) = make_float2(oacc[im][in][2], oacc[im][in][3]);
        }
    }
}

// ---------------------------------------------------------------------------
extern "C" void kernel_launch(void* const* d_in, const int* in_sizes, int n_in,
                              void* d_out, int out_size)
{
    const float* q  = (const float*)d_in[0];
    const float* k  = (const float*)d_in[1];
    const float* v  = (const float*)d_in[2];
    const float* Wq = (const float*)d_in[3];
    const float* Wk = (const float*)d_in[4];
    const float* Wv = (const float*)d_in[5];
    const float* Wo = (const float*)d_in[6];
    float* out = (float*)d_out;

    float *gq, *gk, *gv, *ga, *gwf;
    float2* gst;
    cudaGetSymbolAddress((void**)&gq,  g_Q);
    cudaGetSymbolAddress((void**)&gk,  g_K);
    cudaGetSymbolAddress((void**)&gv,  g_V);
    cudaGetSymbolAddress((void**)&ga,  g_attn);
    cudaGetSymbolAddress((void**)&gwf, g_wts_fallback);
    cudaGetSymbolAddress((void**)&gst, g_stats);

    cudaFuncSetAttribute(av_recompute, cudaFuncAttributeMaxDynamicSharedMemorySize, AV2_SMEM);

    const long outElems = (long)B_ * T_ * D_;
    const long wtsElems = (long)B_ * H_ * T_ * T_;
    float* wts = ((long)out_size >= outElems + wtsElems) ? (out + outElems) : gwf;

    const long TT = (long)T_ * T_;

    // 1) All three projections in one launch
    {
        Batch3 bp;
        bp.A[0] = q;  bp.A[1] = k;  bp.A[2] = v;
        bp.Bm[0] = Wq; bp.Bm[1] = Wk; bp.Bm[2] = Wv;
        bp.C[0] = gq; bp.C[1] = gk; bp.C[2] = gv;
        dim3 g(D_/128, MTOK/128, 3);
        gemm_tf32<128,128,64,32,false,true><<<g, 256>>>(bp, D_, D_, D_, D_, 1.0f, 1,
                                                        0, 0, 0, nullptr);
    }

    // 2) Stats-only score pass: per (b,h) S = (Q K^T)/8 -> (max, sum_exp) tiles
    {
        Batch3 bs;
        bs.A[0] = gq;  bs.A[1] = gq + (long)T_*D_;  bs.A[2] = nullptr;
        bs.Bm[0] = gk; bs.Bm[1] = gk + (long)T_*D_; bs.Bm[2] = nullptr;
        bs.C[0] = wts; bs.C[1] = wts + (long)H_*TT; bs.C[2] = nullptr;
        dim3 g(T_/128, T_/128, B_*H_);
        gemm_tf32<128,128,64,32,true,false><<<g, 256>>>(bs, DK_, D_, D_, T_, 0.125f, H_,
                                                        DK_, DK_, TT, gst);
    }

    // 3) Recompute + normalize + write weights + A@V
    {
        dim3 g(1, T_/128, B_*H_);
        av_recompute<<<g, 256, AV2_SMEM>>>(gq, gk, gv, wts, gst, ga);
    }

    // 4) Output projection
    {
        Batch3 bo;
        bo.A[0] = ga; bo.A[1] = nullptr; bo.A[2] = nullptr;
        bo.Bm[0] = Wo; bo.Bm[1] = nullptr; bo.Bm[2] = nullptr;
        bo.C[0] = out; bo.C[1] = nullptr; bo.C[2] = nullptr;
        dim3 g(D_/128, MTOK/128, 1);
        gemm_tf32<128,128,64,32,false,true><<<g, 256>>>(bo, D_, D_, D_, D_, 1.0f, 1,
                                                        0, 0, 0, nullptr);
    }
}

// round 10
// speedup vs baseline: 1.0032x; 1.0032x over previous
#include <cuda_runtime.h>
#include <math.h>
#include <stdint.h>

// Problem constants
#define B_   2
#define T_   2048
#define D_   768
#define H_   12
#define DK_  64
#define MTOK (B_*T_)          // 4096
#define ROWS_ (B_*H_*T_)      // 49152
#define NTILES 16             // T_/128 score col-tiles per row
#define KPAD 20               // 16 k-words + 4 pad (conflict-free ldmatrix)
#define KP32 36               // 32 k-words + 4 pad (av_fused)

// Scratch (allocation-free: __device__ globals)
__device__ float g_Q[MTOK*D_];
__device__ float g_K[MTOK*D_];
__device__ float g_V[MTOK*D_];
__device__ float g_attn[MTOK*D_];
__device__ float g_wts_fallback[(size_t)B_*H_*T_*T_];
__device__ float2 g_stats[(size_t)ROWS_*NTILES];

struct Batch3 { const float* A[3]; const float* Bm[3]; float* C[3]; };

// ---------------------------------------------------------------------------
__device__ __forceinline__ uint32_t f2tf32(float x) {
    uint32_t u;
    asm("cvt.rna.tf32.f32 %0, %1;" : "=r"(u) : "f"(x));
    return u;
}

__device__ __forceinline__ void mma16n8k8(float* c, const uint32_t* a, const uint32_t* b) {
    asm volatile(
        "mma.sync.aligned.m16n8k8.row.col.f32.tf32.tf32.f32 "
        "{%0,%1,%2,%3}, {%4,%5,%6,%7}, {%8,%9}, {%0,%1,%2,%3};\n"
        : "+f"(c[0]), "+f"(c[1]), "+f"(c[2]), "+f"(c[3])
        : "r"(a[0]), "r"(a[1]), "r"(a[2]), "r"(a[3]), "r"(b[0]), "r"(b[1]));
}

__device__ __forceinline__ void ldsm4(uint32_t& r0, uint32_t& r1, uint32_t& r2, uint32_t& r3,
                                      uint32_t addr) {
    asm volatile("ldmatrix.sync.aligned.m8n8.x4.shared.b16 {%0,%1,%2,%3}, [%4];"
                 : "=r"(r0), "=r"(r1), "=r"(r2), "=r"(r3) : "r"(addr));
}

__device__ __forceinline__ uint32_t cvta_smem(const void* p) {
    return (uint32_t)__cvta_generic_to_shared(p);
}

// ---------------------------------------------------------------------------
// tf32 NT GEMM, k-major smem + ldmatrix + register double buffering.
//   C[m,n] = alpha * sum_k A[m,k]*B[n,k]
// STATS: emit per-(row, 128-col-tile) (max, sum_exp) AND use smem-staged
//        coalesced float4 streaming stores for C.
// ---------------------------------------------------------------------------
template<int BM, int BN, int WM, int WN, bool STATS>
__global__ __launch_bounds__((BM/WM)*(BN/WN)*32) void gemm_tf32(
    Batch3 bat, int K, int lda, int ldb, int ldc, float alpha, int innerCount,
    long aSI, long bSI, long cSI, float2* __restrict__ stats)
{
    constexpr int BK      = 16;
    constexpr int WARPS_M = BM / WM;
    constexpr int WARPS_N = BN / WN;
    constexpr int NT      = WARPS_M * WARPS_N * 32;
    constexpr int MT      = WM / 16;
    constexpr int NTL     = WN / 8;
    constexpr int AIT     = (BM * 4) / NT;
    constexpr int BIT     = (BN * 4) / NT;

    const int bz = blockIdx.z;
    const int bo = bz / innerCount, bi = bz % innerCount;
    const float* A  = bat.A[bo]  + (long)bi * aSI;
    const float* Bm = bat.Bm[bo] + (long)bi * bSI;
    float*       C  = bat.C[bo]  + (long)bi * cSI;

    // flat mainloop buffer: As[2][BM][KPAD] | Bs[2][BN][KPAD]; reused as the
    // C staging buffer (float[64][132]) after the mainloop when STATS.
    __shared__ uint32_t MB[2 * BM * KPAD + 2 * BN * KPAD];
    __shared__ float    sred[WARPS_N][BM];
    uint32_t* Asm = MB;
    uint32_t* Bsm = MB + 2 * BM * KPAD;

    const int tid  = threadIdx.x;
    const int lane = tid & 31;
    const int w    = tid >> 5;
    const int wm   = w % WARPS_M;
    const int wn   = w / WARPS_M;
    const int grp  = lane >> 2;
    const int tig  = lane & 3;

    const int row0 = blockIdx.y * BM;
    const int col0 = blockIdx.x * BN;

    uint32_t aAddr[MT], bAddr[NTL / 2];
    {
        const int rsel  = lane & 15;
        const int csel  = (lane & 16) >> 2;
        const int nsel  = (lane & 7) + ((lane & 16) ? 8 : 0);
        const int cselB = (lane & 8) ? 4 : 0;
#pragma unroll
        for (int im = 0; im < MT; im++)
            aAddr[im] = cvta_smem(&Asm[(wm * WM + im * 16 + rsel) * KPAD + csel]);
#pragma unroll
        for (int ip = 0; ip < NTL / 2; ip++)
            bAddr[ip] = cvta_smem(&Bsm[(wn * WN + ip * 16 + nsel) * KPAD + cselB]);
    }
    constexpr uint32_t ABYTES = BM * KPAD * 4;
    constexpr uint32_t BBYTES = BN * KPAD * 4;

    float acc[MT][NTL][4];
#pragma unroll
    for (int i = 0; i < MT; i++)
#pragma unroll
        for (int j = 0; j < NTL; j++)
#pragma unroll
            for (int e = 0; e < 4; e++) acc[i][j][e] = 0.0f;

    float4 ra[AIT], rb[BIT];

    auto LDG = [&](int k0) {
#pragma unroll
        for (int it = 0; it < AIT; it++) {
            int j = tid + it * NT;
            int m = j >> 2, kq = (j & 3) << 2;
            ra[it] = *reinterpret_cast<const float4*>(&A[(long)(row0 + m) * lda + k0 + kq]);
        }
#pragma unroll
        for (int it = 0; it < BIT; it++) {
            int j = tid + it * NT;
            int n = j >> 2, kq = (j & 3) << 2;
            rb[it] = *reinterpret_cast<const float4*>(&Bm[(long)(col0 + n) * ldb + k0 + kq]);
        }
    };

    auto STS = [&](int buf) {
#pragma unroll
        for (int it = 0; it < AIT; it++) {
            int j = tid + it * NT;
            int m = j >> 2, kq = (j & 3) << 2;
            uint4 s;
            s.x = f2tf32(ra[it].x); s.y = f2tf32(ra[it].y);
            s.z = f2tf32(ra[it].z); s.w = f2tf32(ra[it].w);
            *reinterpret_cast<uint4*>(&Asm[(size_t)buf * BM * KPAD + m * KPAD + kq]) = s;
        }
#pragma unroll
        for (int it = 0; it < BIT; it++) {
            int j = tid + it * NT;
            int n = j >> 2, kq = (j & 3) << 2;
            uint4 s;
            s.x = f2tf32(rb[it].x); s.y = f2tf32(rb[it].y);
            s.z = f2tf32(rb[it].z); s.w = f2tf32(rb[it].w);
            *reinterpret_cast<uint4*>(&Bsm[(size_t)buf * BN * KPAD + n * KPAD + kq]) = s;
        }
    };

    const int nIter = K >> 4;
    LDG(0);
    STS(0);
    __syncthreads();

    for (int t = 0; t < nIter; t++) {
        const int buf = t & 1;
        if (t + 1 < nIter) LDG((t + 1) << 4);
        const uint32_t aoff = buf ? ABYTES : 0u;
        const uint32_t boff = buf ? BBYTES : 0u;
#pragma unroll
        for (int ks = 0; ks < 2; ks++) {
            uint32_t af[MT][4];
            uint32_t bf[NTL][2];
#pragma unroll
            for (int im = 0; im < MT; im++)
                ldsm4(af[im][0], af[im][1], af[im][2], af[im][3],
                      aAddr[im] + aoff + ks * 32);
#pragma unroll
            for (int ip = 0; ip < NTL / 2; ip++) {
                uint32_t r0, r1, r2, r3;
                ldsm4(r0, r1, r2, r3, bAddr[ip] + boff + ks * 32);
                bf[2 * ip][0]     = r0; bf[2 * ip][1]     = r1;
                bf[2 * ip + 1][0] = r2; bf[2 * ip + 1][1] = r3;
            }
#pragma unroll
            for (int im = 0; im < MT; im++)
#pragma unroll
                for (int in = 0; in < NTL; in++)
                    mma16n8k8(acc[im][in], af[im], bf[in]);
        }
        if (t + 1 < nIter) STS(buf ^ 1);
        __syncthreads();
    }

#pragma unroll
    for (int im = 0; im < MT; im++)
#pragma unroll
        for (int in = 0; in < NTL; in++)
#pragma unroll
            for (int e = 0; e < 4; e++) acc[im][in][e] *= alpha;

    if (STATS) {
        float mx[MT][2];
#pragma unroll
        for (int im = 0; im < MT; im++) {
            float m0 = -INFINITY, m1 = -INFINITY;
#pragma unroll
            for (int in = 0; in < NTL; in++) {
                m0 = fmaxf(m0, fmaxf(acc[im][in][0], acc[im][in][1]));
                m1 = fmaxf(m1, fmaxf(acc[im][in][2], acc[im][in][3]));
            }
#pragma unroll
            for (int o = 1; o <= 2; o <<= 1) {
                m0 = fmaxf(m0, __shfl_xor_sync(0xffffffffu, m0, o));
                m1 = fmaxf(m1, __shfl_xor_sync(0xffffffffu, m1, o));
            }
            mx[im][0] = m0; mx[im][1] = m1;
        }
        if (tig == 0) {
#pragma unroll
            for (int im = 0; im < MT; im++) {
                sred[wn][wm * WM + im * 16 + grp]     = mx[im][0];
                sred[wn][wm * WM + im * 16 + grp + 8] = mx[im][1];
            }
        }
        __syncthreads();
        float rmax[MT][2];
#pragma unroll
        for (int im = 0; im < MT; im++)
#pragma unroll
            for (int h = 0; h < 2; h++) {
                int r = wm * WM + im * 16 + grp + h * 8;
                float m = sred[0][r];
#pragma unroll
                for (int ww = 1; ww < WARPS_N; ww++) m = fmaxf(m, sred[ww][r]);
                rmax[im][h] = m;
            }
        __syncthreads();
        float sm[MT][2];
#pragma unroll
        for (int im = 0; im < MT; im++) {
            float s0 = 0.f, s1 = 0.f;
#pragma unroll
            for (int in = 0; in < NTL; in++) {
                s0 += __expf(acc[im][in][0] - rmax[im][0]) + __expf(acc[im][in][1] - rmax[im][0]);
                s1 += __expf(acc[im][in][2] - rmax[im][1]) + __expf(acc[im][in][3] - rmax[im][1]);
            }
#pragma unroll
            for (int o = 1; o <= 2; o <<= 1) {
                s0 += __shfl_xor_sync(0xffffffffu, s0, o);
                s1 += __shfl_xor_sync(0xffffffffu, s1, o);
            }
            sm[im][0] = s0; sm[im][1] = s1;
        }
        if (tig == 0) {
#pragma unroll
            for (int im = 0; im < MT; im++) {
                sred[wn][wm * WM + im * 16 + grp]     = sm[im][0];
                sred[wn][wm * WM + im * 16 + grp + 8] = sm[im][1];
            }
        }
        __syncthreads();
        if (wn == 0 && tig == 0) {
#pragma unroll
            for (int im = 0; im < MT; im++)
#pragma unroll
                for (int h = 0; h < 2; h++) {
                    int r = wm * WM + im * 16 + grp + h * 8;
                    float s = sred[0][r];
#pragma unroll
                    for (int ww = 1; ww < WARPS_N; ww++) s += sred[ww][r];
                    stats[((long)bz * T_ + row0 + r) * NTILES + blockIdx.x] =
                        make_float2(rmax[im][h], s);
                }
        }

        // --- smem-staged coalesced C store (two 64-row halves) ---
        float* stage = reinterpret_cast<float*>(MB);   // [64][132]
#pragma unroll
        for (int half = 0; half < 2; half++) {
            __syncthreads();
            if (wm == half) {
#pragma unroll
                for (int im = 0; im < MT; im++) {
                    int rl = im * 16 + grp;
#pragma unroll
                    for (int in = 0; in < NTL; in++) {
                        int ccl = wn * WN + in * 8 + 2 * tig;
                        *reinterpret_cast<float2*>(&stage[rl * 132 + ccl]) =
                            make_float2(acc[im][in][0], acc[im][in][1]);
                        *reinterpret_cast<float2*>(&stage[(rl + 8) * 132 + ccl]) =
                            make_float2(acc[im][in][2], acc[im][in][3]);
                    }
                }
            }
            __syncthreads();
#pragma unroll
            for (int p = 0; p < 8; p++) {
                int rowl = (tid >> 5) + p * 8;
                int c4   = lane * 4;
                float4 vv = *reinterpret_cast<const float4*>(&stage[rowl * 132 + c4]);
                __stcs(reinterpret_cast<float4*>(
                           &C[(long)(row0 + half * 64 + rowl) * ldc + col0 + c4]), vv);
            }
        }
    } else {
#pragma unroll
        for (int im = 0; im < MT; im++) {
            int r = row0 + wm * WM + im * 16 + grp;
#pragma unroll
            for (int in = 0; in < NTL; in++) {
                int cc = col0 + wn * WN + in * 8 + 2 * tig;
                *reinterpret_cast<float2*>(&C[(long)r       * ldc + cc]) =
                    make_float2(acc[im][in][0], acc[im][in][1]);
                *reinterpret_cast<float2*>(&C[(long)(r + 8) * ldc + cc]) =
                    make_float2(acc[im][in][2], acc[im][in][3]);
            }
        }
    }
}

// ===========================================================================
// Fused stats-reduce + normalize + (W @ V), BK=32, row-contiguous ld/st maps.
// Per (b,h, 128-row block): reduce row stats, read raw scores (128B/row per
// 8 lanes), w = exp(s-M)*inv, write w back (final weights), O += w * V.
// BM=128, BN=64(=DK), BK=32, 8 warps (4 x 2), warp tile 32x32.
// ===========================================================================
#define AV_ABYTES (128 * KP32 * 4)
#define AV_VBYTES (64 * KP32 * 4)
#define AV_SMEM   (2 * AV_ABYTES + 2 * AV_VBYTES + 2 * 128 * 4)

__global__ __launch_bounds__(256) void av_fused(
    float* __restrict__ wts, const float* __restrict__ V,
    const float2* __restrict__ stats, float* __restrict__ O)
{
    constexpr int WARPS_M = 4, WM = 32, WN = 32;
    constexpr int MT = 2, NTL = 4;

    extern __shared__ char dynsm[];
    uint32_t* Asm = reinterpret_cast<uint32_t*>(dynsm);                    // [2][128][KP32]
    uint32_t* Vsm = reinterpret_cast<uint32_t*>(dynsm + 2 * AV_ABYTES);    // [2][64][KP32]
    float*    sM  = reinterpret_cast<float*>(dynsm + 2 * AV_ABYTES + 2 * AV_VBYTES);
    float*    sI  = sM + 128;

    const int z = blockIdx.z;
    const int b = z / H_, h = z % H_;
    const int row0 = blockIdx.y * 128;
    const long gr = (long)z * T_ + row0;

    float* wraw = wts + (long)z * T_ * T_ + (long)row0 * T_;
    const float* Vb = V + (long)b * T_ * D_ + h * DK_;

    const int tid  = threadIdx.x;
    const int lane = tid & 31;
    const int w    = tid >> 5;
    const int wm   = w % WARPS_M;
    const int wn   = w / WARPS_M;
    const int grp  = lane >> 2;
    const int tig  = lane & 3;

    // --- in-kernel stats reduce for this block's 128 rows ---
    if (tid < 128) {
        const float4* sp = reinterpret_cast<const float4*>(stats + (gr + tid) * NTILES);
        float2 vv[NTILES];
#pragma unroll
        for (int i = 0; i < NTILES / 2; i++) {
            float4 t = sp[i];
            vv[2 * i]     = make_float2(t.x, t.y);
            vv[2 * i + 1] = make_float2(t.z, t.w);
        }
        float M = vv[0].x;
#pragma unroll
        for (int i = 1; i < NTILES; i++) M = fmaxf(M, vv[i].x);
        float S = 0.f;
#pragma unroll
        for (int i = 0; i < NTILES; i++) S += __expf(vv[i].x - M) * vv[i].y;
        sM[tid] = M;
        sI[tid] = 1.0f / S;
    }
    __syncthreads();

    // loader maps: weights rows 128B-contiguous per 8 lanes
    const int rowL = tid >> 3;            // 0..31; rows rowL + it*32
    const int kq   = (tid & 7) << 2;      // 0,4,...,28 (16B each; 8 lanes = 128B)
    const int kkV  = tid & 31;            // V loader k row (0..31)
    const int nV8  = (tid >> 5) << 3;     // V loader n base (0..56 step 8)

    float Mv[4], Iv[4];
#pragma unroll
    for (int it = 0; it < 4; it++) {
        Mv[it] = sM[rowL + it * 32];
        Iv[it] = sI[rowL + it * 32];
    }

    // ldmatrix base addresses (buffer 0, kstep 0)
    uint32_t aAddr[MT], vAddr[NTL / 2];
    {
        const int rsel  = lane & 15;
        const int csel  = (lane & 16) >> 2;
        const int nsel  = (lane & 7) + ((lane & 16) ? 8 : 0);
        const int cselB = (lane & 8) ? 4 : 0;
#pragma unroll
        for (int im = 0; im < MT; im++)
            aAddr[im] = cvta_smem(&Asm[(wm * WM + im * 16 + rsel) * KP32 + csel]);
#pragma unroll
        for (int ip = 0; ip < NTL / 2; ip++)
            vAddr[ip] = cvta_smem(&Vsm[(wn * WN + ip * 16 + nsel) * KP32 + cselB]);
    }

    float acc[MT][NTL][4];
#pragma unroll
    for (int i = 0; i < MT; i++)
#pragma unroll
        for (int j = 0; j < NTL; j++)
#pragma unroll
            for (int e = 0; e < 4; e++) acc[i][j][e] = 0.0f;

    float4 sw[4];      // 4 rows (rowL + it*32), one 16B chunk each
    float4 sv[2];      // V: 2 n-quads

    auto LDG = [&](int k0) {
#pragma unroll
        for (int it = 0; it < 4; it++)
            sw[it] = __ldcs(reinterpret_cast<const float4*>(
                &wraw[(long)(rowL + it * 32) * T_ + k0 + kq]));
        sv[0] = *reinterpret_cast<const float4*>(&Vb[(long)(k0 + kkV) * D_ + nV8]);
        sv[1] = *reinterpret_cast<const float4*>(&Vb[(long)(k0 + kkV) * D_ + nV8 + 4]);
    };

    auto PROC = [&](int buf, int k0) {
#pragma unroll
        for (int it = 0; it < 4; it++) {
            const int m = rowL + it * 32;
            float4 t = sw[it];
            float4 wv;
            wv.x = __expf(t.x - Mv[it]) * Iv[it];
            wv.y = __expf(t.y - Mv[it]) * Iv[it];
            wv.z = __expf(t.z - Mv[it]) * Iv[it];
            wv.w = __expf(t.w - Mv[it]) * Iv[it];
            __stcs(reinterpret_cast<float4*>(&wraw[(long)m * T_ + k0 + kq]), wv);
            uint4 s;
            s.x = f2tf32(wv.x); s.y = f2tf32(wv.y);
            s.z = f2tf32(wv.z); s.w = f2tf32(wv.w);
            *reinterpret_cast<uint4*>(&Asm[(size_t)buf * 128 * KP32 + m * KP32 + kq]) = s;
        }
        uint32_t* vd = &Vsm[(size_t)buf * 64 * KP32];
#pragma unroll
        for (int j = 0; j < 2; j++) {
            const float* pv = &sv[j].x;
#pragma unroll
            for (int e = 0; e < 4; e++)
                vd[(nV8 + j * 4 + e) * KP32 + kkV] = f2tf32(pv[e]);
        }
    };

    const int nIter = T_ >> 5;   // 64
    LDG(0);
    PROC(0, 0);
    __syncthreads();

    for (int t = 0; t < nIter; t++) {
        const int buf = t & 1;
        if (t + 1 < nIter) LDG((t + 1) << 5);
        const uint32_t aoff = buf ? (uint32_t)AV_ABYTES : 0u;
        const uint32_t voff = buf ? (uint32_t)AV_VBYTES : 0u;
#pragma unroll
        for (int ks = 0; ks < 4; ks++) {
            uint32_t af[MT][4];
            uint32_t bf[NTL][2];
#pragma unroll
            for (int im = 0; im < MT; im++)
                ldsm4(af[im][0], af[im][1], af[im][2], af[im][3],
                      aAddr[im] + aoff + ks * 32);
#pragma unroll
            for (int ip = 0; ip < NTL / 2; ip++) {
                uint32_t r0v, r1v, r2v, r3v;
                ldsm4(r0v, r1v, r2v, r3v, vAddr[ip] + voff + ks * 32);
                bf[2 * ip][0]     = r0v; bf[2 * ip][1]     = r1v;
                bf[2 * ip + 1][0] = r2v; bf[2 * ip + 1][1] = r3v;
            }
#pragma unroll
            for (int im = 0; im < MT; im++)
#pragma unroll
                for (int in = 0; in < NTL; in++)
                    mma16n8k8(acc[im][in], af[im], bf[in]);
        }
        if (t + 1 < nIter) PROC(buf ^ 1, (t + 1) << 5);
        __syncthreads();
    }

    // write O block [128 x 64] into attn layout [B*T, D] at head offset
#pragma unroll
    for (int im = 0; im < MT; im++) {
        int r = row0 + wm * WM + im * 16 + grp;
#pragma unroll
        for (int in = 0; in < NTL; in++) {
            int cc = wn * WN + in * 8 + 2 * tig;
            float* op = &O[((long)b * T_ + r) * D_ + h * DK_ + cc];
            *reinterpret_cast<float2*>(op)            = make_float2(acc[im][in][0], acc[im][in][1]);
            *reinterpret_cast<float2*>(op + 8LL * D_) = make_float2(acc[im][in][2], acc[im][in][3]);
        }
    }
}

// ---------------------------------------------------------------------------
extern "C" void kernel_launch(void* const* d_in, const int* in_sizes, int n_in,
                              void* d_out, int out_size)
{
    const float* q  = (const float*)d_in[0];
    const float* k  = (const float*)d_in[1];
    const float* v  = (const float*)d_in[2];
    const float* Wq = (const float*)d_in[3];
    const float* Wk = (const float*)d_in[4];
    const float* Wv = (const float*)d_in[5];
    const float* Wo = (const float*)d_in[6];
    float* out = (float*)d_out;

    float *gq, *gk, *gv, *ga, *gwf;
    float2* gst;
    cudaGetSymbolAddress((void**)&gq,  g_Q);
    cudaGetSymbolAddress((void**)&gk,  g_K);
    cudaGetSymbolAddress((void**)&gv,  g_V);
    cudaGetSymbolAddress((void**)&ga,  g_attn);
    cudaGetSymbolAddress((void**)&gwf, g_wts_fallback);
    cudaGetSymbolAddress((void**)&gst, g_stats);

    cudaFuncSetAttribute(av_fused, cudaFuncAttributeMaxDynamicSharedMemorySize, AV_SMEM);

    const long outElems = (long)B_ * T_ * D_;
    const long wtsElems = (long)B_ * H_ * T_ * T_;
    float* wts = ((long)out_size >= outElems + wtsElems) ? (out + outElems) : gwf;

    const long TT = (long)T_ * T_;

    // 1) All three projections in one launch
    {
        Batch3 bp;
        bp.A[0] = q;  bp.A[1] = k;  bp.A[2] = v;
        bp.Bm[0] = Wq; bp.Bm[1] = Wk; bp.Bm[2] = Wv;
        bp.C[0] = gq; bp.C[1] = gk; bp.C[2] = gv;
        dim3 g(D_/128, MTOK/128, 3);
        gemm_tf32<128,128,64,32,false><<<g, 256>>>(bp, D_, D_, D_, D_, 1.0f, 1,
                                                   0, 0, 0, nullptr);
    }

    // 2) Scores + softmax stats (staged coalesced C stores)
    {
        Batch3 bs;
        bs.A[0] = gq;  bs.A[1] = gq + (long)T_*D_;  bs.A[2] = nullptr;
        bs.Bm[0] = gk; bs.Bm[1] = gk + (long)T_*D_; bs.Bm[2] = nullptr;
        bs.C[0] = wts; bs.C[1] = wts + (long)H_*TT; bs.C[2] = nullptr;
        dim3 g(T_/128, T_/128, B_*H_);
        gemm_tf32<128,128,64,32,true><<<g, 256>>>(bs, DK_, D_, D_, T_, 0.125f, H_,
                                                  DK_, DK_, TT, gst);
    }

    // 3) Fused stats-reduce + normalize + A@V (writes final weights + attn)
    {
        dim3 g(1, T_/128, B_*H_);
        av_fused<<<g, 256, AV_SMEM>>>(wts, gv, gst, ga);
    }

    // 4) Output projection
    {
        Batch3 bo;
        bo.A[0] = ga; bo.A[1] = nullptr; bo.A[2] = nullptr;
        bo.Bm[0] = Wo; bo.Bm[1] = nullptr; bo.Bm[2] = nullptr;
        bo.C[0] = out; bo.C[1] = nullptr; bo.C[2] = nullptr;
        dim3 g(D_/128, MTOK/128, 1);
        gemm_tf32<128,128,64,32,false><<<g, 256>>>(bo, D_, D_, D_, D_, 1.0f, 1,
                                                   0, 0, 0, nullptr);
    }
}

// round 11
// speedup vs baseline: 1.0924x; 1.0889x over previous
#include <cuda_runtime.h>
#include <math.h>
#include <stdint.h>

// Problem constants
#define B_   2
#define T_   2048
#define D_   768
#define H_   12
#define DK_  64
#define MTOK (B_*T_)          // 4096
#define ROWS_ (B_*H_*T_)      // 49152
#define NTILES 16             // T_/128 score col-tiles per row
#define KPAD 20               // 16 k-words + 4 pad (conflict-free ldmatrix)
#define KP32 36               // 32 k-words + 4 pad (av_fused)

// Scratch (allocation-free: __device__ globals)
__device__ float g_Q[MTOK*D_];
__device__ float g_K[MTOK*D_];
__device__ float g_V[MTOK*D_];
__device__ float g_attn[MTOK*D_];
__device__ float g_wts_fallback[(size_t)B_*H_*T_*T_];
__device__ float2 g_stats[(size_t)ROWS_*NTILES];

struct Batch3 { const float* A[3]; const float* Bm[3]; float* C[3]; };

// ---------------------------------------------------------------------------
__device__ __forceinline__ uint32_t f2tf32(float x) {
    uint32_t u;
    asm("cvt.rna.tf32.f32 %0, %1;" : "=r"(u) : "f"(x));
    return u;
}

__device__ __forceinline__ void mma16n8k8(float* c, const uint32_t* a, const uint32_t* b) {
    asm volatile(
        "mma.sync.aligned.m16n8k8.row.col.f32.tf32.tf32.f32 "
        "{%0,%1,%2,%3}, {%4,%5,%6,%7}, {%8,%9}, {%0,%1,%2,%3};\n"
        : "+f"(c[0]), "+f"(c[1]), "+f"(c[2]), "+f"(c[3])
        : "r"(a[0]), "r"(a[1]), "r"(a[2]), "r"(a[3]), "r"(b[0]), "r"(b[1]));
}

__device__ __forceinline__ void ldsm4(uint32_t& r0, uint32_t& r1, uint32_t& r2, uint32_t& r3,
                                      uint32_t addr) {
    asm volatile("ldmatrix.sync.aligned.m8n8.x4.shared.b16 {%0,%1,%2,%3}, [%4];"
                 : "=r"(r0), "=r"(r1), "=r"(r2), "=r"(r3) : "r"(addr));
}

__device__ __forceinline__ uint32_t cvta_smem(const void* p) {
    return (uint32_t)__cvta_generic_to_shared(p);
}

// ---------------------------------------------------------------------------
// tf32 NT GEMM, k-major smem + ldmatrix + register double buffering.
//   C[m,n] = alpha * sum_k A[m,k]*B[n,k]   (proven R8 shape; plain stores)
// ---------------------------------------------------------------------------
template<int BM, int BN, int WM, int WN>
__global__ __launch_bounds__((BM/WM)*(BN/WN)*32) void gemm_tf32(
    Batch3 bat, int K, int lda, int ldb, int ldc, float alpha, int innerCount,
    long aSI, long bSI, long cSI)
{
    constexpr int BK      = 16;
    constexpr int WARPS_M = BM / WM;
    constexpr int WARPS_N = BN / WN;
    constexpr int NT      = WARPS_M * WARPS_N * 32;
    constexpr int MT      = WM / 16;
    constexpr int NTL     = WN / 8;
    constexpr int AIT     = (BM * 4) / NT;
    constexpr int BIT     = (BN * 4) / NT;

    const int bz = blockIdx.z;
    const int bo = bz / innerCount, bi = bz % innerCount;
    const float* A  = bat.A[bo]  + (long)bi * aSI;
    const float* Bm = bat.Bm[bo] + (long)bi * bSI;
    float*       C  = bat.C[bo]  + (long)bi * cSI;

    __shared__ uint32_t As[2][BM][KPAD];
    __shared__ uint32_t Bs[2][BN][KPAD];

    const int tid  = threadIdx.x;
    const int lane = tid & 31;
    const int w    = tid >> 5;
    const int wm   = w % WARPS_M;
    const int wn   = w / WARPS_M;
    const int grp  = lane >> 2;
    const int tig  = lane & 3;

    const int row0 = blockIdx.y * BM;
    const int col0 = blockIdx.x * BN;

    uint32_t aAddr[MT], bAddr[NTL / 2];
    {
        const int rsel  = lane & 15;
        const int csel  = (lane & 16) >> 2;
        const int nsel  = (lane & 7) + ((lane & 16) ? 8 : 0);
        const int cselB = (lane & 8) ? 4 : 0;
#pragma unroll
        for (int im = 0; im < MT; im++)
            aAddr[im] = cvta_smem(&As[0][wm * WM + im * 16 + rsel][csel]);
#pragma unroll
        for (int ip = 0; ip < NTL / 2; ip++)
            bAddr[ip] = cvta_smem(&Bs[0][wn * WN + ip * 16 + nsel][cselB]);
    }
    constexpr uint32_t ABYTES = BM * KPAD * 4;
    constexpr uint32_t BBYTES = BN * KPAD * 4;

    float acc[MT][NTL][4];
#pragma unroll
    for (int i = 0; i < MT; i++)
#pragma unroll
        for (int j = 0; j < NTL; j++)
#pragma unroll
            for (int e = 0; e < 4; e++) acc[i][j][e] = 0.0f;

    float4 ra[AIT], rb[BIT];

    auto LDG = [&](int k0) {
#pragma unroll
        for (int it = 0; it < AIT; it++) {
            int j = tid + it * NT;
            int m = j >> 2, kq = (j & 3) << 2;
            ra[it] = *reinterpret_cast<const float4*>(&A[(long)(row0 + m) * lda + k0 + kq]);
        }
#pragma unroll
        for (int it = 0; it < BIT; it++) {
            int j = tid + it * NT;
            int n = j >> 2, kq = (j & 3) << 2;
            rb[it] = *reinterpret_cast<const float4*>(&Bm[(long)(col0 + n) * ldb + k0 + kq]);
        }
    };

    auto STS = [&](int buf) {
#pragma unroll
        for (int it = 0; it < AIT; it++) {
            int j = tid + it * NT;
            int m = j >> 2, kq = (j & 3) << 2;
            uint4 s;
            s.x = f2tf32(ra[it].x); s.y = f2tf32(ra[it].y);
            s.z = f2tf32(ra[it].z); s.w = f2tf32(ra[it].w);
            *reinterpret_cast<uint4*>(&As[buf][m][kq]) = s;
        }
#pragma unroll
        for (int it = 0; it < BIT; it++) {
            int j = tid + it * NT;
            int n = j >> 2, kq = (j & 3) << 2;
            uint4 s;
            s.x = f2tf32(rb[it].x); s.y = f2tf32(rb[it].y);
            s.z = f2tf32(rb[it].z); s.w = f2tf32(rb[it].w);
            *reinterpret_cast<uint4*>(&Bs[buf][n][kq]) = s;
        }
    };

    const int nIter = K >> 4;
    LDG(0);
    STS(0);
    __syncthreads();

    for (int t = 0; t < nIter; t++) {
        const int buf = t & 1;
        if (t + 1 < nIter) LDG((t + 1) << 4);
        const uint32_t aoff = buf ? ABYTES : 0u;
        const uint32_t boff = buf ? BBYTES : 0u;
#pragma unroll
        for (int ks = 0; ks < 2; ks++) {
            uint32_t af[MT][4];
            uint32_t bf[NTL][2];
#pragma unroll
            for (int im = 0; im < MT; im++)
                ldsm4(af[im][0], af[im][1], af[im][2], af[im][3],
                      aAddr[im] + aoff + ks * 32);
#pragma unroll
            for (int ip = 0; ip < NTL / 2; ip++) {
                uint32_t r0, r1, r2, r3;
                ldsm4(r0, r1, r2, r3, bAddr[ip] + boff + ks * 32);
                bf[2 * ip][0]     = r0; bf[2 * ip][1]     = r1;
                bf[2 * ip + 1][0] = r2; bf[2 * ip + 1][1] = r3;
            }
#pragma unroll
            for (int im = 0; im < MT; im++)
#pragma unroll
                for (int in = 0; in < NTL; in++)
                    mma16n8k8(acc[im][in], af[im], bf[in]);
        }
        if (t + 1 < nIter) STS(buf ^ 1);
        __syncthreads();
    }

#pragma unroll
    for (int im = 0; im < MT; im++) {
        int r = row0 + wm * WM + im * 16 + grp;
#pragma unroll
        for (int in = 0; in < NTL; in++) {
            int cc = col0 + wn * WN + in * 8 + 2 * tig;
            *reinterpret_cast<float2*>(&C[(long)r       * ldc + cc]) =
                make_float2(alpha * acc[im][in][0], alpha * acc[im][in][1]);
            *reinterpret_cast<float2*>(&C[(long)(r + 8) * ldc + cc]) =
                make_float2(alpha * acc[im][in][2], alpha * acc[im][in][3]);
        }
    }
}

// ===========================================================================
// score_stats: per (b,h) S = (Q K^T)/8 with WM=16, WN=128 warp tiling.
// Each tig-quad owns full rows -> stats (max, sum_exp) via pure shfl,
// zero epilogue syncs, zero smem reduction.
// 8 warps stacked along M; BM=BN=128, K=DK_=64.
// ===========================================================================
__global__ __launch_bounds__(256) void score_stats(
    const float* __restrict__ Qg, const float* __restrict__ Kg,
    float* __restrict__ wts, float2* __restrict__ stats)
{
    const int z = blockIdx.z;
    const int b = z / H_, h = z % H_;
    const float* A  = Qg + (long)b * T_ * D_ + h * DK_;
    const float* Bm = Kg + (long)b * T_ * D_ + h * DK_;
    float* C = wts + (long)z * T_ * T_;

    __shared__ uint32_t As[2][128][KPAD];
    __shared__ uint32_t Bs[2][128][KPAD];

    const int tid  = threadIdx.x;
    const int lane = tid & 31;
    const int wm   = tid >> 5;       // warp = M slab (16 rows)
    const int grp  = lane >> 2;
    const int tig  = lane & 3;

    const int row0 = blockIdx.y * 128;
    const int col0 = blockIdx.x * 128;

    // ldmatrix addresses
    uint32_t aAddr, bAddr[8];
    {
        const int rsel  = lane & 15;
        const int csel  = (lane & 16) >> 2;
        const int nsel  = (lane & 7) + ((lane & 16) ? 8 : 0);
        const int cselB = (lane & 8) ? 4 : 0;
        aAddr = cvta_smem(&As[0][wm * 16 + rsel][csel]);
#pragma unroll
        for (int ip = 0; ip < 8; ip++)
            bAddr[ip] = cvta_smem(&Bs[0][ip * 16 + nsel][cselB]);
    }
    constexpr uint32_t TBYTES = 128 * KPAD * 4;

    float acc[16][4];
#pragma unroll
    for (int i = 0; i < 16; i++)
#pragma unroll
        for (int e = 0; e < 4; e++) acc[i][e] = 0.0f;

    float4 ra[2], rb[2];
    auto LDG = [&](int k0) {
#pragma unroll
        for (int it = 0; it < 2; it++) {
            int j = tid + it * 256;
            int m = j >> 2, kq = (j & 3) << 2;
            ra[it] = *reinterpret_cast<const float4*>(&A[(long)(row0 + m) * D_ + k0 + kq]);
            rb[it] = *reinterpret_cast<const float4*>(&Bm[(long)(col0 + m) * D_ + k0 + kq]);
        }
    };
    auto STS = [&](int buf) {
#pragma unroll
        for (int it = 0; it < 2; it++) {
            int j = tid + it * 256;
            int m = j >> 2, kq = (j & 3) << 2;
            uint4 s;
            s.x = f2tf32(ra[it].x); s.y = f2tf32(ra[it].y);
            s.z = f2tf32(ra[it].z); s.w = f2tf32(ra[it].w);
            *reinterpret_cast<uint4*>(&As[buf][m][kq]) = s;
            uint4 v;
            v.x = f2tf32(rb[it].x); v.y = f2tf32(rb[it].y);
            v.z = f2tf32(rb[it].z); v.w = f2tf32(rb[it].w);
            *reinterpret_cast<uint4*>(&Bs[buf][m][kq]) = v;
        }
    };

    const int nIter = DK_ >> 4;   // 4
    LDG(0);
    STS(0);
    __syncthreads();

    for (int t = 0; t < nIter; t++) {
        const int buf = t & 1;
        if (t + 1 < nIter) LDG((t + 1) << 4);
        const uint32_t off = buf ? TBYTES : 0u;
#pragma unroll
        for (int ks = 0; ks < 2; ks++) {
            uint32_t af[4];
            ldsm4(af[0], af[1], af[2], af[3], aAddr + off + ks * 32);
#pragma unroll
            for (int iph = 0; iph < 2; iph++) {
                uint32_t bf[8][2];
#pragma unroll
                for (int ip = 0; ip < 4; ip++) {
                    uint32_t r0, r1, r2, r3;
                    ldsm4(r0, r1, r2, r3, bAddr[iph * 4 + ip] + off + ks * 32);
                    bf[2 * ip][0]     = r0; bf[2 * ip][1]     = r1;
                    bf[2 * ip + 1][0] = r2; bf[2 * ip + 1][1] = r3;
                }
#pragma unroll
                for (int in = 0; in < 8; in++)
                    mma16n8k8(acc[iph * 8 + in], af, bf[in]);
            }
        }
        if (t + 1 < nIter) STS(buf ^ 1);
        __syncthreads();
    }

    // scale by 1/8
#pragma unroll
    for (int in = 0; in < 16; in++)
#pragma unroll
        for (int e = 0; e < 4; e++) acc[in][e] *= 0.125f;

    // --- pure-shfl row stats (quad owns full row) ---
    float m0 = -INFINITY, m1 = -INFINITY;
#pragma unroll
    for (int in = 0; in < 16; in++) {
        m0 = fmaxf(m0, fmaxf(acc[in][0], acc[in][1]));
        m1 = fmaxf(m1, fmaxf(acc[in][2], acc[in][3]));
    }
#pragma unroll
    for (int o = 1; o <= 2; o <<= 1) {
        m0 = fmaxf(m0, __shfl_xor_sync(0xffffffffu, m0, o));
        m1 = fmaxf(m1, __shfl_xor_sync(0xffffffffu, m1, o));
    }
    float s0 = 0.f, s1 = 0.f;
#pragma unroll
    for (int in = 0; in < 16; in++) {
        s0 += __expf(acc[in][0] - m0) + __expf(acc[in][1] - m0);
        s1 += __expf(acc[in][2] - m1) + __expf(acc[in][3] - m1);
    }
#pragma unroll
    for (int o = 1; o <= 2; o <<= 1) {
        s0 += __shfl_xor_sync(0xffffffffu, s0, o);
        s1 += __shfl_xor_sync(0xffffffffu, s1, o);
    }
    const int rlo = wm * 16 + grp;
    if (tig == 0) {
        stats[((long)z * T_ + row0 + rlo)     * NTILES + blockIdx.x] = make_float2(m0, s0);
        stats[((long)z * T_ + row0 + rlo + 8) * NTILES + blockIdx.x] = make_float2(m1, s1);
    }

    // --- C store ---
#pragma unroll
    for (int in = 0; in < 16; in++) {
        int cc = col0 + in * 8 + 2 * tig;
        *reinterpret_cast<float2*>(&C[(long)(row0 + rlo)     * T_ + cc]) =
            make_float2(acc[in][0], acc[in][1]);
        *reinterpret_cast<float2*>(&C[(long)(row0 + rlo + 8) * T_ + cc]) =
            make_float2(acc[in][2], acc[in][3]);
    }
}

// ===========================================================================
// Fused stats-reduce + normalize + (W @ V), BK=32 (R8-proven, unchanged).
// ===========================================================================
#define AV_ABYTES (128 * KP32 * 4)
#define AV_VBYTES (64 * KP32 * 4)
#define AV_SMEM   (2 * AV_ABYTES + 2 * AV_VBYTES + 2 * 128 * 4)

__global__ __launch_bounds__(256) void av_fused(
    float* __restrict__ wts, const float* __restrict__ V,
    const float2* __restrict__ stats, float* __restrict__ O)
{
    constexpr int WARPS_M = 4, WM = 32, WN = 32;
    constexpr int MT = 2, NTL = 4;

    extern __shared__ char dynsm[];
    uint32_t* Asm = reinterpret_cast<uint32_t*>(dynsm);                    // [2][128][KP32]
    uint32_t* Vsm = reinterpret_cast<uint32_t*>(dynsm + 2 * AV_ABYTES);    // [2][64][KP32]
    float*    sM  = reinterpret_cast<float*>(dynsm + 2 * AV_ABYTES + 2 * AV_VBYTES);
    float*    sI  = sM + 128;

    const int z = blockIdx.z;
    const int b = z / H_, h = z % H_;
    const int row0 = blockIdx.y * 128;
    const long gr = (long)z * T_ + row0;

    float* wraw = wts + (long)z * T_ * T_ + (long)row0 * T_;
    const float* Vb = V + (long)b * T_ * D_ + h * DK_;

    const int tid  = threadIdx.x;
    const int lane = tid & 31;
    const int w    = tid >> 5;
    const int wm   = w % WARPS_M;
    const int wn   = w / WARPS_M;
    const int grp  = lane >> 2;
    const int tig  = lane & 3;

    if (tid < 128) {
        const float4* sp = reinterpret_cast<const float4*>(stats + (gr + tid) * NTILES);
        float2 vv[NTILES];
#pragma unroll
        for (int i = 0; i < NTILES / 2; i++) {
            float4 t = sp[i];
            vv[2 * i]     = make_float2(t.x, t.y);
            vv[2 * i + 1] = make_float2(t.z, t.w);
        }
        float M = vv[0].x;
#pragma unroll
        for (int i = 1; i < NTILES; i++) M = fmaxf(M, vv[i].x);
        float S = 0.f;
#pragma unroll
        for (int i = 0; i < NTILES; i++) S += __expf(vv[i].x - M) * vv[i].y;
        sM[tid] = M;
        sI[tid] = 1.0f / S;
    }
    __syncthreads();

    const int r0  = tid >> 2;
    const int kqL = (tid & 3) << 2;
    const int kkV = tid & 31;
    const int nV8 = (tid >> 5) << 3;

    const float M0 = sM[r0],      I0 = sI[r0];
    const float M1 = sM[r0 + 64], I1 = sI[r0 + 64];

    uint32_t aAddr[MT], vAddr[NTL / 2];
    {
        const int rsel  = lane & 15;
        const int csel  = (lane & 16) >> 2;
        const int nsel  = (lane & 7) + ((lane & 16) ? 8 : 0);
        const int cselB = (lane & 8) ? 4 : 0;
#pragma unroll
        for (int im = 0; im < MT; im++)
            aAddr[im] = cvta_smem(&Asm[(wm * WM + im * 16 + rsel) * KP32 + csel]);
#pragma unroll
        for (int ip = 0; ip < NTL / 2; ip++)
            vAddr[ip] = cvta_smem(&Vsm[(wn * WN + ip * 16 + nsel) * KP32 + cselB]);
    }

    float acc[MT][NTL][4];
#pragma unroll
    for (int i = 0; i < MT; i++)
#pragma unroll
        for (int j = 0; j < NTL; j++)
#pragma unroll
            for (int e = 0; e < 4; e++) acc[i][j][e] = 0.0f;

    float4 sw[2][2];
    float4 sv[2];

    auto LDG = [&](int k0) {
#pragma unroll
        for (int rr = 0; rr < 2; rr++)
#pragma unroll
            for (int cc = 0; cc < 2; cc++)
                sw[rr][cc] = __ldcs(reinterpret_cast<const float4*>(
                    &wraw[(long)(r0 + rr * 64) * T_ + k0 + kqL + cc * 16]));
        sv[0] = *reinterpret_cast<const float4*>(&Vb[(long)(k0 + kkV) * D_ + nV8]);
        sv[1] = *reinterpret_cast<const float4*>(&Vb[(long)(k0 + kkV) * D_ + nV8 + 4]);
    };

    auto PROC = [&](int buf, int k0) {
#pragma unroll
        for (int rr = 0; rr < 2; rr++) {
            const int m = r0 + rr * 64;
            const float Mr = rr ? M1 : M0;
            const float Ir = rr ? I1 : I0;
#pragma unroll
            for (int cc = 0; cc < 2; cc++) {
                float4 t = sw[rr][cc];
                float4 wv;
                wv.x = __expf(t.x - Mr) * Ir;
                wv.y = __expf(t.y - Mr) * Ir;
                wv.z = __expf(t.z - Mr) * Ir;
                wv.w = __expf(t.w - Mr) * Ir;
                __stcs(reinterpret_cast<float4*>(&wraw[(long)m * T_ + k0 + kqL + cc * 16]), wv);
                uint4 s;
                s.x = f2tf32(wv.x); s.y = f2tf32(wv.y);
                s.z = f2tf32(wv.z); s.w = f2tf32(wv.w);
                *reinterpret_cast<uint4*>(&Asm[(size_t)buf * 128 * KP32 + m * KP32 + kqL + cc * 16]) = s;
            }
        }
        uint32_t* vd = &Vsm[(size_t)buf * 64 * KP32];
#pragma unroll
        for (int j = 0; j < 2; j++) {
            const float* pv = &sv[j].x;
#pragma unroll
            for (int e = 0; e < 4; e++)
                vd[(nV8 + j * 4 + e) * KP32 + kkV] = f2tf32(pv[e]);
        }
    };

    const int nIter = T_ >> 5;   // 64
    LDG(0);
    PROC(0, 0);
    __syncthreads();

    for (int t = 0; t < nIter; t++) {
        const int buf = t & 1;
        if (t + 1 < nIter) LDG((t + 1) << 5);
        const uint32_t aoff = buf ? (uint32_t)AV_ABYTES : 0u;
        const uint32_t voff = buf ? (uint32_t)AV_VBYTES : 0u;
#pragma unroll
        for (int ks = 0; ks < 4; ks++) {
            uint32_t af[MT][4];
            uint32_t bf[NTL][2];
#pragma unroll
            for (int im = 0; im < MT; im++)
                ldsm4(af[im][0], af[im][1], af[im][2], af[im][3],
                      aAddr[im] + aoff + ks * 32);
#pragma unroll
            for (int ip = 0; ip < NTL / 2; ip++) {
                uint32_t r0v, r1v, r2v, r3v;
                ldsm4(r0v, r1v, r2v, r3v, vAddr[ip] + voff + ks * 32);
                bf[2 * ip][0]     = r0v; bf[2 * ip][1]     = r1v;
                bf[2 * ip + 1][0] = r2v; bf[2 * ip + 1][1] = r3v;
            }
#pragma unroll
            for (int im = 0; im < MT; im++)
#pragma unroll
                for (int in = 0; in < NTL; in++)
                    mma16n8k8(acc[im][in], af[im], bf[in]);
        }
        if (t + 1 < nIter) PROC(buf ^ 1, (t + 1) << 5);
        __syncthreads();
    }

#pragma unroll
    for (int im = 0; im < MT; im++) {
        int r = row0 + wm * WM + im * 16 + grp;
#pragma unroll
        for (int in = 0; in < NTL; in++) {
            int cc = wn * WN + in * 8 + 2 * tig;
            float* op = &O[((long)b * T_ + r) * D_ + h * DK_ + cc];
            *reinterpret_cast<float2*>(op)            = make_float2(acc[im][in][0], acc[im][in][1]);
            *reinterpret_cast<float2*>(op + 8LL * D_) = make_float2(acc[im][in][2], acc[im][in][3]);
        }
    }
}

// ---------------------------------------------------------------------------
extern "C" void kernel_launch(void* const* d_in, const int* in_sizes, int n_in,
                              void* d_out, int out_size)
{
    const float* q  = (const float*)d_in[0];
    const float* k  = (const float*)d_in[1];
    const float* v  = (const float*)d_in[2];
    const float* Wq = (const float*)d_in[3];
    const float* Wk = (const float*)d_in[4];
    const float* Wv = (const float*)d_in[5];
    const float* Wo = (const float*)d_in[6];
    float* out = (float*)d_out;

    float *gq, *gk, *gv, *ga, *gwf;
    float2* gst;
    cudaGetSymbolAddress((void**)&gq,  g_Q);
    cudaGetSymbolAddress((void**)&gk,  g_K);
    cudaGetSymbolAddress((void**)&gv,  g_V);
    cudaGetSymbolAddress((void**)&ga,  g_attn);
    cudaGetSymbolAddress((void**)&gwf, g_wts_fallback);
    cudaGetSymbolAddress((void**)&gst, g_stats);

    cudaFuncSetAttribute(av_fused, cudaFuncAttributeMaxDynamicSharedMemorySize, AV_SMEM);

    const long outElems = (long)B_ * T_ * D_;
    const long wtsElems = (long)B_ * H_ * T_ * T_;
    float* wts = ((long)out_size >= outElems + wtsElems) ? (out + outElems) : gwf;

    // 1) All three projections in one launch
    {
        Batch3 bp;
        bp.A[0] = q;  bp.A[1] = k;  bp.A[2] = v;
        bp.Bm[0] = Wq; bp.Bm[1] = Wk; bp.Bm[2] = Wv;
        bp.C[0] = gq; bp.C[1] = gk; bp.C[2] = gv;
        dim3 g(D_/128, MTOK/128, 3);
        gemm_tf32<128,128,64,32><<<g, 256>>>(bp, D_, D_, D_, D_, 1.0f, 1, 0, 0, 0);
    }

    // 2) Scores + softmax stats (shfl-only epilogue)
    {
        dim3 g(T_/128, T_/128, B_*H_);
        score_stats<<<g, 256>>>(gq, gk, wts, gst);
    }

    // 3) Fused stats-reduce + normalize + A@V (writes final weights + attn)
    {
        dim3 g(1, T_/128, B_*H_);
        av_fused<<<g, 256, AV_SMEM>>>(wts, gv, gst, ga);
    }

    // 4) Output projection (128x64 tiles -> 384 CTAs)
    {
        Batch3 bo;
        bo.A[0] = ga; bo.A[1] = nullptr; bo.A[2] = nullptr;
        bo.Bm[0] = Wo; bo.Bm[1] = nullptr; bo.Bm[2] = nullptr;
        bo.C[0] = out; bo.C[1] = nullptr; bo.C[2] = nullptr;
        dim3 g(D_/64, MTOK/128, 1);
        gemm_tf32<128,64,32,32><<<g, 256>>>(bo, D_, D_, D_, D_, 1.0f, 1, 0, 0, 0);
    }
}